// round 10
// baseline (speedup 1.0000x reference)
#include <cuda_runtime.h>
#include <cuda_fp16.h>
#include <cstdint>
#include <cstddef>

// Problem constants
#define NV     4096
#define KIN    512
#define DOUT   64
#define NHEAD  8
#define LALPHA 0.2f

// ---------------------------------------------------------------------------
// Device scratch (no allocations allowed)
// ---------------------------------------------------------------------------
__device__ __align__(128) float    g_Wh[(size_t)NHEAD * NV * DOUT];    // fp32 [H][N][64]
__device__ __align__(128) __half   g_Wh16[(size_t)NHEAD * NV * DOUT];  // fp16 [H][N][64]
__device__ __align__(128) __half   g_x16[(size_t)NV * KIN];            // fp16 [N][512]
__device__ __align__(128) __half   g_W16[(size_t)NHEAD * KIN * DOUT];  // fp16 [H][512][64]
__device__ __align__(128) float    g_f1[NHEAD * NV];
__device__ __align__(128) float    g_f2[NHEAD * NV];
__device__ __align__(128) unsigned g_F2maxU[NHEAD];                    // monotone-key max
__device__ __align__(128) unsigned g_mask[(size_t)NV * (NV / 32)];     // [N][128] words

// ---------------------------------------------------------------------------
// sm_80-era tensor-core PTX (valid on base sm_103 target)
// ---------------------------------------------------------------------------
__device__ __forceinline__ uint32_t smem_u32(const void* p) {
    uint32_t a;
    asm("{ .reg .u64 t; cvta.to.shared.u64 t, %1; cvt.u32.u64 %0, t; }"
        : "=r"(a) : "l"(p));
    return a;
}

#define LDSM_X4(r, a) \
    asm volatile("ldmatrix.sync.aligned.m8n8.x4.shared.b16 {%0,%1,%2,%3}, [%4];" \
        : "=r"((r)[0]), "=r"((r)[1]), "=r"((r)[2]), "=r"((r)[3]) : "r"(a))

#define LDSM_X4T(r, a) \
    asm volatile("ldmatrix.sync.aligned.m8n8.x4.trans.shared.b16 {%0,%1,%2,%3}, [%4];" \
        : "=r"((r)[0]), "=r"((r)[1]), "=r"((r)[2]), "=r"((r)[3]) : "r"(a))

#define MMA16816(d, a, b) \
    asm volatile("mma.sync.aligned.m16n8k16.row.col.f32.f16.f16.f32 " \
        "{%0,%1,%2,%3}, {%4,%5,%6,%7}, {%8,%9}, {%0,%1,%2,%3};" \
        : "+f"((d)[0]), "+f"((d)[1]), "+f"((d)[2]), "+f"((d)[3]) \
        : "r"((a)[0]), "r"((a)[1]), "r"((a)[2]), "r"((a)[3]), \
          "r"((b)[0]), "r"((b)[1]))

// order-preserving float -> unsigned key (for atomicMax)
__device__ __forceinline__ unsigned fkey(float f) {
    unsigned b = __float_as_uint(f);
    return (b & 0x80000000u) ? ~b : (b | 0x80000000u);
}
__device__ __forceinline__ float funkey(unsigned k) {
    return __uint_as_float((k & 0x80000000u) ? (k & 0x7fffffffu) : ~k);
}

// ---------------------------------------------------------------------------
// prep: x -> fp16, W -> fp16 (W is [H][IN][OUT] = [h][k][o] already), init max
// ---------------------------------------------------------------------------
__global__ __launch_bounds__(256) void prep_kernel(const float* __restrict__ x,
                                                   const float* __restrict__ W) {
    int tid = blockIdx.x * 256 + threadIdx.x;
    int nt  = gridDim.x * 256;
    for (int i = tid; i < NV * KIN / 2; i += nt) {
        float2 v = ((const float2*)x)[i];
        ((__half2*)g_x16)[i] = __floats2half2_rn(v.x, v.y);
    }
    for (int i = tid; i < NHEAD * KIN * DOUT / 2; i += nt) {
        float2 v = ((const float2*)W)[i];
        ((__half2*)g_W16)[i] = __floats2half2_rn(v.x, v.y);
    }
    if (tid < NHEAD) g_F2maxU[tid] = 0u;   // key of -inf
}

// ---------------------------------------------------------------------------
// Kernel: adj -> bitmask (word w covers m = w*32..+31, bit = lane)
// ---------------------------------------------------------------------------
__global__ __launch_bounds__(256) void mask_kernel(const int* __restrict__ adj) {
    int gw   = (blockIdx.x * 256 + threadIdx.x) >> 5;
    int lane = threadIdx.x & 31;
    int nw   = (gridDim.x * 256) >> 5;
    for (int w = gw; w < NV * (NV / 32); w += nw) {
        int v = adj[(size_t)w * 32 + lane];
        unsigned b = __ballot_sync(0xffffffffu, v > 0);
        if (lane == 0) g_mask[w] = b;
    }
}

// ---------------------------------------------------------------------------
// Kernel 1: Wh = x @ W per head, HMMA. CTA = (128 rows, head). 8 warps:
// 4 M-blocks x 2 N-blocks. K = 512 in 8 chunks of 64.
// ---------------------------------------------------------------------------
#define XP 72
#define WP 72

__global__ __launch_bounds__(256, 2) void wh16_kernel() {
    __shared__ __half xs[128 * XP];
    __shared__ __half ws[64 * WP];

    const int h  = blockIdx.y;
    const int n0 = blockIdx.x * 128;
    const int tid = threadIdx.x, wid = tid >> 5, lane = tid & 31;

    const uint32_t Xb = smem_u32(xs);
    const uint32_t Wb = smem_u32(ws);

    const int mblk = (wid & 3) * 32, nblk = (wid >> 2) * 32;
    float acc[2][4][4];
#pragma unroll
    for (int i = 0; i < 2; i++)
#pragma unroll
        for (int j = 0; j < 4; j++)
#pragma unroll
            for (int q = 0; q < 4; q++) acc[i][j][q] = 0.f;

    for (int k0 = 0; k0 < KIN; k0 += 64) {
        // x tile: 128 rows x 64 halves
#pragma unroll
        for (int l = 0; l < 4; l++) {
            int idx = tid + l * 256;            // 0..1023
            int r = idx >> 3, q = idx & 7;
            uint4 v = *(const uint4*)(g_x16 + (size_t)(n0 + r) * KIN + k0 + q * 8);
            *(uint4*)(xs + r * XP + q * 8) = v;
        }
        // W tile: 64 k-rows x 64 halves
#pragma unroll
        for (int l = 0; l < 2; l++) {
            int idx = tid + l * 256;            // 0..511
            int r = idx >> 3, q = idx & 7;
            uint4 v = *(const uint4*)(g_W16 + ((size_t)h * KIN + k0 + r) * DOUT + q * 8);
            *(uint4*)(ws + r * WP + q * 8) = v;
        }
        __syncthreads();

        const int rsel = lane & 15, csel = (lane >> 4) << 3;
#pragma unroll
        for (int kk = 0; kk < 64; kk += 16) {
            unsigned a0[4], a1[4], b0[4], b1[4];
            LDSM_X4 (a0, Xb + ((mblk      + rsel) * XP + kk + csel) * 2);
            LDSM_X4 (a1, Xb + ((mblk + 16 + rsel) * XP + kk + csel) * 2);
            LDSM_X4T(b0, Wb + ((kk + rsel) * WP + nblk      + csel) * 2);
            LDSM_X4T(b1, Wb + ((kk + rsel) * WP + nblk + 16 + csel) * 2);
            MMA16816(acc[0][0], a0, b0 + 0);
            MMA16816(acc[0][1], a0, b0 + 2);
            MMA16816(acc[0][2], a0, b1 + 0);
            MMA16816(acc[0][3], a0, b1 + 2);
            MMA16816(acc[1][0], a1, b0 + 0);
            MMA16816(acc[1][1], a1, b0 + 2);
            MMA16816(acc[1][2], a1, b1 + 0);
            MMA16816(acc[1][3], a1, b1 + 2);
        }
        __syncthreads();
    }

    // epilogue: fragment (mi, nj): rows mblk+mi*16+g, +8; cols nblk+nj*8+2t
    const int g = lane >> 2, t2 = (lane & 3) * 2;
    float*  of  = g_Wh   + ((size_t)h * NV + n0) * DOUT;
    __half* o16 = g_Wh16 + ((size_t)h * NV + n0) * DOUT;
#pragma unroll
    for (int mi = 0; mi < 2; mi++)
#pragma unroll
        for (int nj = 0; nj < 4; nj++) {
            int rA = mblk + mi * 16 + g, rB = rA + 8;
            int col = nblk + nj * 8 + t2;
            *(float2*)(of + (size_t)rA * DOUT + col) =
                make_float2(acc[mi][nj][0], acc[mi][nj][1]);
            *(float2*)(of + (size_t)rB * DOUT + col) =
                make_float2(acc[mi][nj][2], acc[mi][nj][3]);
            *(__half2*)(o16 + (size_t)rA * DOUT + col) =
                __floats2half2_rn(acc[mi][nj][0], acc[mi][nj][1]);
            *(__half2*)(o16 + (size_t)rB * DOUT + col) =
                __floats2half2_rn(acc[mi][nj][2], acc[mi][nj][3]);
        }
}

// ---------------------------------------------------------------------------
// Kernel 2: f1/f2 per (h,n) + atomic head max of f2
// ---------------------------------------------------------------------------
__global__ __launch_bounds__(256) void fvec_kernel(const float* __restrict__ a1,
                                                   const float* __restrict__ a2) {
    int gw = (blockIdx.x * 256 + threadIdx.x) >> 5;
    int lane = threadIdx.x & 31;
    if (gw >= NHEAD * NV) return;
    int h = gw & 7, n = gw >> 3;
    const float* wr = g_Wh + ((size_t)h * NV + n) * DOUT;
    float w0 = wr[lane], w1 = wr[lane + 32];
    float s1 = w0 * a1[h * DOUT + lane] + w1 * a1[h * DOUT + lane + 32];
    float s2 = w0 * a2[h * DOUT + lane] + w1 * a2[h * DOUT + lane + 32];
#pragma unroll
    for (int off = 16; off; off >>= 1) {
        s1 += __shfl_xor_sync(0xffffffffu, s1, off);
        s2 += __shfl_xor_sync(0xffffffffu, s2, off);
    }
    if (lane == 0) {
        g_f1[h * NV + n] = s1;
        g_f2[h * NV + n] = s2;
        atomicMax(&g_F2maxU[h], fkey(s2));
    }
}

// ---------------------------------------------------------------------------
// Kernel 3: fused softmax + aggregation via mma.sync.
//   p = exp(lrelu(f1+f2) - Mr) = max(c1*E1[m], c2*E05[m])  (exact, all <= 1)
// Mask read directly from gmem (each word used exactly once per CTA).
// smem ~61KB -> 2 CTAs/SM.
// ---------------------------------------------------------------------------
#define PP 72

#define SM_E1   0
#define SM_E05  16384
#define SM_P    32768     /* 128*72*2 = 18432 */
#define SM_W    51200     /* 64*72*2 = 9216  */
#define SM_C1   60416     /* 128 f */
#define SM_C2   60928     /* 128 f */
#define SM_DEN  61440     /* 128 f */
#define SMEM_ATT 61952

__global__ __launch_bounds__(256, 2) void attn_mma(float* __restrict__ out) {
    extern __shared__ unsigned char sm[];
    float* E1s  = (float*)(sm + SM_E1);
    float* E05s = (float*)(sm + SM_E05);
    float* c1s  = (float*)(sm + SM_C1);
    float* c2s  = (float*)(sm + SM_C2);
    float* denS = (float*)(sm + SM_DEN);

    const int h = blockIdx.x, n0 = blockIdx.y * 128;
    const int tid = threadIdx.x, wid = tid >> 5, lane = tid & 31;

    const uint32_t Pb = smem_u32(sm + SM_P);
    const uint32_t Wb = smem_u32(sm + SM_W);

    // stage E1/E05 and per-row constants
    const float F2m = funkey(g_F2maxU[h]);
    for (int i = tid; i < NV; i += 256) {
        float d = g_f2[(size_t)h * NV + i] - F2m;
        E1s[i]  = __expf(d);
        E05s[i] = __expf(LALPHA * d);
    }
    if (tid < 128) {
        float t = g_f1[(size_t)h * NV + n0 + tid] + F2m;
        float Mr = fmaxf(t, LALPHA * t);
        c1s[tid] = __expf(t - Mr);
        c2s[tid] = __expf(LALPHA * t - Mr);
    }
    __syncthreads();

    float den[16];
#pragma unroll
    for (int k = 0; k < 16; k++) den[k] = 0.f;

    const int mblk = (wid & 3) * 32, nblk = (wid >> 2) * 32;
    float acc[2][4][4];
#pragma unroll
    for (int i = 0; i < 2; i++)
#pragma unroll
        for (int j = 0; j < 4; j++)
#pragma unroll
            for (int q = 0; q < 4; q++) acc[i][j][q] = 0.f;

    const __half*    WhH = g_Wh16 + (size_t)h * NV * DOUT;
    const unsigned*  MK  = g_mask + (size_t)n0 * 128;

    for (int c = 0; c < 64; c++) {
        // Wh chunk rows into registers first (MLP)
        uint4 bv[2];
#pragma unroll
        for (int l = 0; l < 2; l++) {
            int idx = tid + l * 256;
            int m = idx >> 3, q = idx & 7;
            bv[l] = *(const uint4*)(WhH + (size_t)(c * 64 + m) * DOUT + q * 8);
        }

        // P tile: warp wid -> rows wid*16..+15; lane -> m-pair (2*lane, 2*lane+1)
        float2 e1p  = *(const float2*)(E1s  + c * 64 + 2 * lane);
        float2 e05p = *(const float2*)(E05s + c * 64 + 2 * lane);
#pragma unroll
        for (int k = 0; k < 16; k++) {
            int r = wid * 16 + k;
            unsigned w = MK[r * 128 + c * 2 + (lane >> 4)];
            float C1 = c1s[r], C2 = c2s[r];
            float p0 = fmaxf(C1 * e1p.x,  C2 * e05p.x);
            float p1 = fmaxf(C1 * e1p.y,  C2 * e05p.y);
            p0 = ((w >> ((2 * lane) & 31)) & 1u) ? p0 : 0.f;
            p1 = ((w >> ((2 * lane + 1) & 31)) & 1u) ? p1 : 0.f;
            den[k] += p0 + p1;
            *(__half2*)(sm + SM_P + (r * PP + 2 * lane) * 2) =
                __floats2half2_rn(p0, p1);
        }

        // Wh tile store
#pragma unroll
        for (int l = 0; l < 2; l++) {
            int idx = tid + l * 256;
            int m = idx >> 3, q = idx & 7;
            *(uint4*)(sm + SM_W + (m * PP + q * 8) * 2) = bv[l];
        }
        __syncthreads();

        // HMMA: M=128 N=64 K=64
        const int rsel = lane & 15, csel = (lane >> 4) << 3;
#pragma unroll
        for (int k0 = 0; k0 < 64; k0 += 16) {
            unsigned a0[4], a1[4], b0[4], b1[4];
            LDSM_X4 (a0, Pb + ((mblk      + rsel) * PP + k0 + csel) * 2);
            LDSM_X4 (a1, Pb + ((mblk + 16 + rsel) * PP + k0 + csel) * 2);
            LDSM_X4T(b0, Wb + ((k0 + rsel) * PP + nblk      + csel) * 2);
            LDSM_X4T(b1, Wb + ((k0 + rsel) * PP + nblk + 16 + csel) * 2);
            MMA16816(acc[0][0], a0, b0 + 0);
            MMA16816(acc[0][1], a0, b0 + 2);
            MMA16816(acc[0][2], a0, b1 + 0);
            MMA16816(acc[0][3], a0, b1 + 2);
            MMA16816(acc[1][0], a1, b0 + 0);
            MMA16816(acc[1][1], a1, b0 + 2);
            MMA16816(acc[1][2], a1, b1 + 0);
            MMA16816(acc[1][3], a1, b1 + 2);
        }
        __syncthreads();
    }

    // denominators -> smem
#pragma unroll
    for (int k = 0; k < 16; k++) {
        float v = den[k];
#pragma unroll
        for (int sh = 16; sh; sh >>= 1) v += __shfl_xor_sync(0xffffffffu, v, sh);
        if (lane == 0) denS[wid * 16 + k] = v;
    }
    __syncthreads();

    // epilogue
    const int g = lane >> 2, t2 = (lane & 3) * 2;
    float inv[4];
#pragma unroll
    for (int i = 0; i < 4; i++) {
        float d = denS[mblk + i * 8 + g];
        inv[i] = d > 0.f ? 1.f / d : 0.f;
    }
#pragma unroll
    for (int mi = 0; mi < 2; mi++)
#pragma unroll
        for (int nj = 0; nj < 4; nj++) {
            int rA = mblk + mi * 16 + g;
            int rB = rA + 8;
            int col = nblk + nj * 8 + t2;
            float ia = inv[mi * 2 + 0], ib = inv[mi * 2 + 1];
            *(float2*)(out + (size_t)(n0 + rA) * (NHEAD * DOUT) + h * DOUT + col) =
                make_float2(acc[mi][nj][0] * ia, acc[mi][nj][1] * ia);
            *(float2*)(out + (size_t)(n0 + rB) * (NHEAD * DOUT) + h * DOUT + col) =
                make_float2(acc[mi][nj][2] * ib, acc[mi][nj][3] * ib);
        }
}

// ---------------------------------------------------------------------------
extern "C" void kernel_launch(void* const* d_in, const int* in_sizes, int n_in,
                              void* d_out, int out_size) {
    (void)in_sizes; (void)n_in; (void)out_size;
    const float* x   = (const float*)d_in[0];
    const int*   adj = (const int*)d_in[1];
    const float* W   = (const float*)d_in[2];
    const float* a1  = (const float*)d_in[3];
    const float* a2  = (const float*)d_in[4];
    float* out = (float*)d_out;

    cudaFuncSetAttribute(attn_mma, cudaFuncAttributeMaxDynamicSharedMemorySize,
                         SMEM_ATT);

    prep_kernel<<<256, 256>>>(x, W);
    mask_kernel<<<512, 256>>>(adj);
    wh16_kernel<<<dim3(32, 8), 256>>>();
    fvec_kernel<<<4096, 256>>>(a1, a2);
    attn_mma<<<dim3(8, 32), 256, SMEM_ATT>>>(out);
}

// round 14
// speedup vs baseline: 1.5631x; 1.5631x over previous
#include <cuda_runtime.h>
#include <cuda_fp16.h>
#include <cstdint>
#include <cstddef>

// Problem constants
#define NV     4096
#define KIN    512
#define DOUT   64
#define NHEAD  8
#define LALPHA 0.2f

// ---------------------------------------------------------------------------
// Device scratch (no allocations allowed)
// ---------------------------------------------------------------------------
__device__ __align__(128) float    g_Wh[(size_t)NHEAD * NV * DOUT];    // fp32 [H][N][64]
__device__ __align__(128) __half   g_Wh16[(size_t)NHEAD * NV * DOUT];  // fp16 [H][N][64]
__device__ __align__(128) __half   g_x16[(size_t)NV * KIN];            // fp16 [N][512]
__device__ __align__(128) __half   g_W16[(size_t)NHEAD * KIN * DOUT];  // fp16 [H][512][64]
__device__ __align__(128) float    g_f1[NHEAD * NV];
__device__ __align__(128) float    g_f2[NHEAD * NV];
__device__ __align__(128) float    g_E1[NHEAD * NV];                   // exp(f2-F2max)
__device__ __align__(128) float    g_E05[NHEAD * NV];                  // exp(.2(f2-F2max))
__device__ __align__(128) unsigned g_F2maxU[NHEAD];                    // monotone-key max
__device__ __align__(128) unsigned g_mask[(size_t)NV * (NV / 32)];     // [N][128] words

// ---------------------------------------------------------------------------
// sm_80-era tensor-core PTX (valid on base sm_103 target)
// ---------------------------------------------------------------------------
__device__ __forceinline__ uint32_t smem_u32(const void* p) {
    uint32_t a;
    asm("{ .reg .u64 t; cvta.to.shared.u64 t, %1; cvt.u32.u64 %0, t; }"
        : "=r"(a) : "l"(p));
    return a;
}

#define LDSM_X4(r, a) \
    asm volatile("ldmatrix.sync.aligned.m8n8.x4.shared.b16 {%0,%1,%2,%3}, [%4];" \
        : "=r"((r)[0]), "=r"((r)[1]), "=r"((r)[2]), "=r"((r)[3]) : "r"(a))

#define LDSM_X4T(r, a) \
    asm volatile("ldmatrix.sync.aligned.m8n8.x4.trans.shared.b16 {%0,%1,%2,%3}, [%4];" \
        : "=r"((r)[0]), "=r"((r)[1]), "=r"((r)[2]), "=r"((r)[3]) : "r"(a))

#define MMA16816(d, a, b) \
    asm volatile("mma.sync.aligned.m16n8k16.row.col.f32.f16.f16.f32 " \
        "{%0,%1,%2,%3}, {%4,%5,%6,%7}, {%8,%9}, {%0,%1,%2,%3};" \
        : "+f"((d)[0]), "+f"((d)[1]), "+f"((d)[2]), "+f"((d)[3]) \
        : "r"((a)[0]), "r"((a)[1]), "r"((a)[2]), "r"((a)[3]), \
          "r"((b)[0]), "r"((b)[1]))

// order-preserving float <-> unsigned key (for atomicMax)
__device__ __forceinline__ unsigned fkey(float f) {
    unsigned b = __float_as_uint(f);
    return (b & 0x80000000u) ? ~b : (b | 0x80000000u);
}
__device__ __forceinline__ float funkey(unsigned k) {
    return __uint_as_float((k & 0x80000000u) ? (k & 0x7fffffffu) : ~k);
}

// ---------------------------------------------------------------------------
// prep: x -> fp16, W -> fp16, init head-max keys
// ---------------------------------------------------------------------------
__global__ __launch_bounds__(256) void prep_kernel(const float* __restrict__ x,
                                                   const float* __restrict__ W) {
    int tid = blockIdx.x * 256 + threadIdx.x;
    int nt  = gridDim.x * 256;
    for (int i = tid; i < NV * KIN / 2; i += nt) {
        float2 v = ((const float2*)x)[i];
        ((__half2*)g_x16)[i] = __floats2half2_rn(v.x, v.y);
    }
    for (int i = tid; i < NHEAD * KIN * DOUT / 2; i += nt) {
        float2 v = ((const float2*)W)[i];
        ((__half2*)g_W16)[i] = __floats2half2_rn(v.x, v.y);
    }
    if (tid < NHEAD) g_F2maxU[tid] = fkey(-3.4e38f);
}

// ---------------------------------------------------------------------------
// adj -> bitmask (word w covers m = w*32..+31, bit = lane)
// ---------------------------------------------------------------------------
__global__ __launch_bounds__(256) void mask_kernel(const int* __restrict__ adj) {
    int gw   = (blockIdx.x * 256 + threadIdx.x) >> 5;
    int lane = threadIdx.x & 31;
    int nw   = (gridDim.x * 256) >> 5;
    for (int w = gw; w < NV * (NV / 32); w += nw) {
        int v = adj[(size_t)w * 32 + lane];
        unsigned b = __ballot_sync(0xffffffffu, v > 0);
        if (lane == 0) g_mask[w] = b;
    }
}

// ---------------------------------------------------------------------------
// Kernel 1: Wh = x @ W per head via HMMA. CTA = (128 rows, head).
// ---------------------------------------------------------------------------
#define XP 72
#define WP 72

__global__ __launch_bounds__(256, 2) void wh16_kernel() {
    __shared__ __half xs[128 * XP];
    __shared__ __half ws[64 * WP];

    const int h  = blockIdx.y;
    const int n0 = blockIdx.x * 128;
    const int tid = threadIdx.x, wid = tid >> 5, lane = tid & 31;

    const uint32_t Xb = smem_u32(xs);
    const uint32_t Wb = smem_u32(ws);

    const int mblk = (wid & 3) * 32, nblk = (wid >> 2) * 32;
    float acc[2][4][4];
#pragma unroll
    for (int i = 0; i < 2; i++)
#pragma unroll
        for (int j = 0; j < 4; j++)
#pragma unroll
            for (int q = 0; q < 4; q++) acc[i][j][q] = 0.f;

    for (int k0 = 0; k0 < KIN; k0 += 64) {
#pragma unroll
        for (int l = 0; l < 4; l++) {
            int idx = tid + l * 256;
            int r = idx >> 3, q = idx & 7;
            uint4 v = *(const uint4*)(g_x16 + (size_t)(n0 + r) * KIN + k0 + q * 8);
            *(uint4*)(xs + r * XP + q * 8) = v;
        }
#pragma unroll
        for (int l = 0; l < 2; l++) {
            int idx = tid + l * 256;
            int r = idx >> 3, q = idx & 7;
            uint4 v = *(const uint4*)(g_W16 + ((size_t)h * KIN + k0 + r) * DOUT + q * 8);
            *(uint4*)(ws + r * WP + q * 8) = v;
        }
        __syncthreads();

        const int rsel = lane & 15, csel = (lane >> 4) << 3;
#pragma unroll
        for (int kk = 0; kk < 64; kk += 16) {
            unsigned a0[4], a1[4], b0[4], b1[4];
            LDSM_X4 (a0, Xb + ((mblk      + rsel) * XP + kk + csel) * 2);
            LDSM_X4 (a1, Xb + ((mblk + 16 + rsel) * XP + kk + csel) * 2);
            LDSM_X4T(b0, Wb + ((kk + rsel) * WP + nblk      + csel) * 2);
            LDSM_X4T(b1, Wb + ((kk + rsel) * WP + nblk + 16 + csel) * 2);
            MMA16816(acc[0][0], a0, b0 + 0);
            MMA16816(acc[0][1], a0, b0 + 2);
            MMA16816(acc[0][2], a0, b1 + 0);
            MMA16816(acc[0][3], a0, b1 + 2);
            MMA16816(acc[1][0], a1, b0 + 0);
            MMA16816(acc[1][1], a1, b0 + 2);
            MMA16816(acc[1][2], a1, b1 + 0);
            MMA16816(acc[1][3], a1, b1 + 2);
        }
        __syncthreads();
    }

    const int g = lane >> 2, t2 = (lane & 3) * 2;
    float*  of  = g_Wh   + ((size_t)h * NV + n0) * DOUT;
    __half* o16 = g_Wh16 + ((size_t)h * NV + n0) * DOUT;
#pragma unroll
    for (int mi = 0; mi < 2; mi++)
#pragma unroll
        for (int nj = 0; nj < 4; nj++) {
            int rA = mblk + mi * 16 + g, rB = rA + 8;
            int col = nblk + nj * 8 + t2;
            *(float2*)(of + (size_t)rA * DOUT + col) =
                make_float2(acc[mi][nj][0], acc[mi][nj][1]);
            *(float2*)(of + (size_t)rB * DOUT + col) =
                make_float2(acc[mi][nj][2], acc[mi][nj][3]);
            *(__half2*)(o16 + (size_t)rA * DOUT + col) =
                __floats2half2_rn(acc[mi][nj][0], acc[mi][nj][1]);
            *(__half2*)(o16 + (size_t)rB * DOUT + col) =
                __floats2half2_rn(acc[mi][nj][2], acc[mi][nj][3]);
        }
}

// ---------------------------------------------------------------------------
// Kernel 2: f1/f2, 2 rows per warp (half-warp per row, float4 lanes)
// NHEAD*NV/2 = 16384 warps -> 2048 blocks of 256.
// ---------------------------------------------------------------------------
__global__ __launch_bounds__(256) void fvec_kernel(const float* __restrict__ a1,
                                                   const float* __restrict__ a2) {
    int gw = (blockIdx.x * 256 + threadIdx.x) >> 5;          // 0..16383
    int lane = threadIdx.x & 31;
    int half = lane >> 4, l4 = lane & 15;
    int flat = gw * 2 + half;                                 // h*NV + n, 0..32767
    int h = flat >> 12;

    const float4 wv = *(const float4*)(g_Wh + (size_t)flat * DOUT + l4 * 4);
    const float4 av = *(const float4*)(a1 + h * DOUT + l4 * 4);
    const float4 bv = *(const float4*)(a2 + h * DOUT + l4 * 4);
    float s1 = wv.x * av.x + wv.y * av.y + wv.z * av.z + wv.w * av.w;
    float s2 = wv.x * bv.x + wv.y * bv.y + wv.z * bv.z + wv.w * bv.w;
#pragma unroll
    for (int off = 8; off; off >>= 1) {
        s1 += __shfl_xor_sync(0xffffffffu, s1, off);
        s2 += __shfl_xor_sync(0xffffffffu, s2, off);
    }
    if (l4 == 0) {
        g_f1[flat] = s1;
        g_f2[flat] = s2;
        atomicMax(&g_F2maxU[h], fkey(s2));
    }
}

// ---------------------------------------------------------------------------
// Kernel: E1/E05 precompute (once per head, after fvec)
// ---------------------------------------------------------------------------
__global__ __launch_bounds__(256) void e_kernel() {
    int i = blockIdx.x * 256 + threadIdx.x;                  // 0..32767
    int h = i >> 12;
    float d = g_f2[i] - funkey(g_F2maxU[h]);
    g_E1[i]  = __expf(d);
    g_E05[i] = __expf(LALPHA * d);
}

// ---------------------------------------------------------------------------
// Kernel 3: fused softmax + aggregation via mma.sync.
//   p = exp(lrelu(f1+f2) - Mr) = max(c1*E1[m], c2*E05[m])  (exact, all <= 1)
// Mask staged in smem (hot P-gen path); E1/E05 from gmem (L1-hot broadcasts).
// smem ~94.7KB -> 2 CTAs/SM on GB300's 228KB carveout.
// ---------------------------------------------------------------------------
#define PP 72

#define SM_MASK 0         /* 65536 */
#define SM_P    65536     /* 128*72*2 = 18432 */
#define SM_W    83968     /* 64*72*2 = 9216  */
#define SM_C1   93184     /* 128 f */
#define SM_C2   93696     /* 128 f */
#define SM_DEN  94208     /* 128 f */
#define SMEM_ATT 94720

__global__ __launch_bounds__(256, 2) void attn_mma(float* __restrict__ out) {
    extern __shared__ unsigned char sm[];
    unsigned* maskS = (unsigned*)(sm + SM_MASK);
    float*    c1s   = (float*)(sm + SM_C1);
    float*    c2s   = (float*)(sm + SM_C2);
    float*    denS  = (float*)(sm + SM_DEN);

    const int h = blockIdx.x, n0 = blockIdx.y * 128;
    const int tid = threadIdx.x, wid = tid >> 5, lane = tid & 31;

    const uint32_t Pb = smem_u32(sm + SM_P);
    const uint32_t Wb = smem_u32(sm + SM_W);

    // stage mask rows + per-row softmax constants
#pragma unroll
    for (int l = 0; l < 16; l++) {
        int i = tid + l * 256;
        ((uint4*)maskS)[i] = ((const uint4*)(g_mask + (size_t)n0 * 128))[i];
    }
    if (tid < 128) {
        float t = g_f1[(size_t)h * NV + n0 + tid] + funkey(g_F2maxU[h]);
        float Mr = fmaxf(t, LALPHA * t);
        c1s[tid] = __expf(t - Mr);
        c2s[tid] = __expf(LALPHA * t - Mr);
    }
    __syncthreads();

    float den[16];
#pragma unroll
    for (int k = 0; k < 16; k++) den[k] = 0.f;

    const int mblk = (wid & 3) * 32, nblk = (wid >> 2) * 32;
    float acc[2][4][4];
#pragma unroll
    for (int i = 0; i < 2; i++)
#pragma unroll
        for (int j = 0; j < 4; j++)
#pragma unroll
            for (int q = 0; q < 4; q++) acc[i][j][q] = 0.f;

    const __half* WhH = g_Wh16 + (size_t)h * NV * DOUT;
    const float*  E1g = g_E1  + (size_t)h * NV;
    const float*  E5g = g_E05 + (size_t)h * NV;

    for (int c = 0; c < 64; c++) {
        // Wh chunk rows into registers first (MLP)
        uint4 bv[2];
#pragma unroll
        for (int l = 0; l < 2; l++) {
            int idx = tid + l * 256;
            int m = idx >> 3, q = idx & 7;
            bv[l] = *(const uint4*)(WhH + (size_t)(c * 64 + m) * DOUT + q * 8);
        }

        // P tile: warp wid -> rows wid*16..+15; lane -> m-pair (2*lane, 2*lane+1)
        float2 e1p = *(const float2*)(E1g + c * 64 + 2 * lane);
        float2 e5p = *(const float2*)(E5g + c * 64 + 2 * lane);
#pragma unroll
        for (int k = 0; k < 16; k++) {
            int r = wid * 16 + k;
            unsigned w = maskS[r * 128 + c * 2 + (lane >> 4)];
            float C1 = c1s[r], C2 = c2s[r];
            float p0 = fmaxf(C1 * e1p.x, C2 * e5p.x);
            float p1 = fmaxf(C1 * e1p.y, C2 * e5p.y);
            p0 = ((w >> ((2 * lane) & 31)) & 1u) ? p0 : 0.f;
            p1 = ((w >> ((2 * lane + 1) & 31)) & 1u) ? p1 : 0.f;
            den[k] += p0 + p1;
            *(__half2*)(sm + SM_P + (r * PP + 2 * lane) * 2) =
                __floats2half2_rn(p0, p1);
        }

        // Wh tile store
#pragma unroll
        for (int l = 0; l < 2; l++) {
            int idx = tid + l * 256;
            int m = idx >> 3, q = idx & 7;
            *(uint4*)(sm + SM_W + (m * PP + q * 8) * 2) = bv[l];
        }
        __syncthreads();

        // HMMA: M=128 N=64 K=64
        const int rsel = lane & 15, csel = (lane >> 4) << 3;
#pragma unroll
        for (int k0 = 0; k0 < 64; k0 += 16) {
            unsigned a0[4], a1[4], b0[4], b1[4];
            LDSM_X4 (a0, Pb + ((mblk      + rsel) * PP + k0 + csel) * 2);
            LDSM_X4 (a1, Pb + ((mblk + 16 + rsel) * PP + k0 + csel) * 2);
            LDSM_X4T(b0, Wb + ((k0 + rsel) * PP + nblk      + csel) * 2);
            LDSM_X4T(b1, Wb + ((k0 + rsel) * PP + nblk + 16 + csel) * 2);
            MMA16816(acc[0][0], a0, b0 + 0);
            MMA16816(acc[0][1], a0, b0 + 2);
            MMA16816(acc[0][2], a0, b1 + 0);
            MMA16816(acc[0][3], a0, b1 + 2);
            MMA16816(acc[1][0], a1, b0 + 0);
            MMA16816(acc[1][1], a1, b0 + 2);
            MMA16816(acc[1][2], a1, b1 + 0);
            MMA16816(acc[1][3], a1, b1 + 2);
        }
        __syncthreads();
    }

    // denominators -> smem
#pragma unroll
    for (int k = 0; k < 16; k++) {
        float v = den[k];
#pragma unroll
        for (int sh = 16; sh; sh >>= 1) v += __shfl_xor_sync(0xffffffffu, v, sh);
        if (lane == 0) denS[wid * 16 + k] = v;
    }
    __syncthreads();

    // epilogue
    const int g = lane >> 2, t2 = (lane & 3) * 2;
    float inv[4];
#pragma unroll
    for (int i = 0; i < 4; i++) {
        float d = denS[mblk + i * 8 + g];
        inv[i] = d > 0.f ? 1.f / d : 0.f;
    }
#pragma unroll
    for (int mi = 0; mi < 2; mi++)
#pragma unroll
        for (int nj = 0; nj < 4; nj++) {
            int rA = mblk + mi * 16 + g;
            int rB = rA + 8;
            int col = nblk + nj * 8 + t2;
            float ia = inv[mi * 2 + 0], ib = inv[mi * 2 + 1];
            *(float2*)(out + (size_t)(n0 + rA) * (NHEAD * DOUT) + h * DOUT + col) =
                make_float2(acc[mi][nj][0] * ia, acc[mi][nj][1] * ia);
            *(float2*)(out + (size_t)(n0 + rB) * (NHEAD * DOUT) + h * DOUT + col) =
                make_float2(acc[mi][nj][2] * ib, acc[mi][nj][3] * ib);
        }
}

// ---------------------------------------------------------------------------
extern "C" void kernel_launch(void* const* d_in, const int* in_sizes, int n_in,
                              void* d_out, int out_size) {
    (void)in_sizes; (void)n_in; (void)out_size;
    const float* x   = (const float*)d_in[0];
    const int*   adj = (const int*)d_in[1];
    const float* W   = (const float*)d_in[2];
    const float* a1  = (const float*)d_in[3];
    const float* a2  = (const float*)d_in[4];
    float* out = (float*)d_out;

    cudaFuncSetAttribute(attn_mma, cudaFuncAttributeMaxDynamicSharedMemorySize,
                         SMEM_ATT);

    prep_kernel<<<256, 256>>>(x, W);
    mask_kernel<<<512, 256>>>(adj);
    wh16_kernel<<<dim3(32, 8), 256>>>();
    fvec_kernel<<<2048, 256>>>(a1, a2);
    e_kernel<<<128, 256>>>();
    attn_mma<<<dim3(8, 32), 256, SMEM_ATT>>>(out);
}

// round 16
// speedup vs baseline: 1.5940x; 1.0197x over previous
#include <cuda_runtime.h>
#include <cuda_fp16.h>
#include <cstdint>
#include <cstddef>

// Problem constants
#define NV     4096
#define KIN    512
#define DOUT   64
#define NHEAD  8
#define LALPHA 0.2f

// ---------------------------------------------------------------------------
// Device scratch (no allocations allowed)
// ---------------------------------------------------------------------------
__device__ __align__(128) float    g_Wh[(size_t)NHEAD * NV * DOUT];    // fp32 [H][N][64]
__device__ __align__(128) __half   g_Wh16[(size_t)NHEAD * NV * DOUT];  // fp16 [H][N][64]
__device__ __align__(128) __half   g_x16[(size_t)NV * KIN];            // fp16 [N][512]
__device__ __align__(128) __half   g_W16[(size_t)NHEAD * KIN * DOUT];  // fp16 [H][512][64]
__device__ __align__(128) float    g_f1[NHEAD * NV];
__device__ __align__(128) float    g_f2[NHEAD * NV];
__device__ __align__(128) float    g_E1[NHEAD * NV];                   // exp(f2-F2max)
__device__ __align__(128) float    g_E05[NHEAD * NV];                  // exp(.2(f2-F2max))
__device__ __align__(128) unsigned g_F2maxU[NHEAD];                    // monotone-key max
__device__ __align__(128) unsigned g_mask[(size_t)(NV / 32) * NV];     // TRANSPOSED [w][n]

// ---------------------------------------------------------------------------
// sm_80-era tensor-core PTX (valid on base sm_103 target)
// ---------------------------------------------------------------------------
__device__ __forceinline__ uint32_t smem_u32(const void* p) {
    uint32_t a;
    asm("{ .reg .u64 t; cvta.to.shared.u64 t, %1; cvt.u32.u64 %0, t; }"
        : "=r"(a) : "l"(p));
    return a;
}

#define LDSM_X4(r, a) \
    asm volatile("ldmatrix.sync.aligned.m8n8.x4.shared.b16 {%0,%1,%2,%3}, [%4];" \
        : "=r"((r)[0]), "=r"((r)[1]), "=r"((r)[2]), "=r"((r)[3]) : "r"(a))

#define LDSM_X4T(r, a) \
    asm volatile("ldmatrix.sync.aligned.m8n8.x4.trans.shared.b16 {%0,%1,%2,%3}, [%4];" \
        : "=r"((r)[0]), "=r"((r)[1]), "=r"((r)[2]), "=r"((r)[3]) : "r"(a))

#define MMA16816(d, a, b) \
    asm volatile("mma.sync.aligned.m16n8k16.row.col.f32.f16.f16.f32 " \
        "{%0,%1,%2,%3}, {%4,%5,%6,%7}, {%8,%9}, {%0,%1,%2,%3};" \
        : "+f"((d)[0]), "+f"((d)[1]), "+f"((d)[2]), "+f"((d)[3]) \
        : "r"((a)[0]), "r"((a)[1]), "r"((a)[2]), "r"((a)[3]), \
          "r"((b)[0]), "r"((b)[1]))

// order-preserving float <-> unsigned key (for atomicMax)
__device__ __forceinline__ unsigned fkey(float f) {
    unsigned b = __float_as_uint(f);
    return (b & 0x80000000u) ? ~b : (b | 0x80000000u);
}
__device__ __forceinline__ float funkey(unsigned k) {
    return __uint_as_float((k & 0x80000000u) ? (k & 0x7fffffffu) : ~k);
}

// ---------------------------------------------------------------------------
// prep: x -> fp16, W -> fp16, init head-max keys
// ---------------------------------------------------------------------------
__global__ __launch_bounds__(256) void prep_kernel(const float* __restrict__ x,
                                                   const float* __restrict__ W) {
    int tid = blockIdx.x * 256 + threadIdx.x;
    int nt  = gridDim.x * 256;
    for (int i = tid; i < NV * KIN / 2; i += nt) {
        float2 v = ((const float2*)x)[i];
        ((__half2*)g_x16)[i] = __floats2half2_rn(v.x, v.y);
    }
    for (int i = tid; i < NHEAD * KIN * DOUT / 2; i += nt) {
        float2 v = ((const float2*)W)[i];
        ((__half2*)g_W16)[i] = __floats2half2_rn(v.x, v.y);
    }
    if (tid < NHEAD) g_F2maxU[tid] = fkey(-3.4e38f);
}

// ---------------------------------------------------------------------------
// adj -> TRANSPOSED bitmask: g_mask[w * NV + n], word w covers m = w*32..+31
// ---------------------------------------------------------------------------
__global__ __launch_bounds__(256) void mask_kernel(const int* __restrict__ adj) {
    int gw   = (blockIdx.x * 256 + threadIdx.x) >> 5;
    int lane = threadIdx.x & 31;
    int nw   = (gridDim.x * 256) >> 5;
    for (int wl = gw; wl < NV * (NV / 32); wl += nw) {
        int v = adj[(size_t)wl * 32 + lane];
        unsigned b = __ballot_sync(0xffffffffu, v > 0);
        if (lane == 0) {
            int n = wl >> 7, w = wl & 127;
            g_mask[(size_t)w * NV + n] = b;
        }
    }
}

// ---------------------------------------------------------------------------
// Kernel 1: Wh = x @ W per head via HMMA + fused f1/f2 epilogue.
// CTA = (128 rows, head). 8 warps: 4 M-blocks x 2 N-blocks.
// ---------------------------------------------------------------------------
#define XP 72
#define WP 72

__global__ __launch_bounds__(256, 2) void wh16_kernel(const float* __restrict__ a1,
                                                      const float* __restrict__ a2) {
    __shared__ __half xs[128 * XP];
    __shared__ __half ws[64 * WP];

    const int h  = blockIdx.y;
    const int n0 = blockIdx.x * 128;
    const int tid = threadIdx.x, wid = tid >> 5, lane = tid & 31;

    const uint32_t Xb = smem_u32(xs);
    const uint32_t Wb = smem_u32(ws);

    const int mblk = (wid & 3) * 32, nblk = (wid >> 2) * 32;
    float acc[2][4][4];
#pragma unroll
    for (int i = 0; i < 2; i++)
#pragma unroll
        for (int j = 0; j < 4; j++)
#pragma unroll
            for (int q = 0; q < 4; q++) acc[i][j][q] = 0.f;

    for (int k0 = 0; k0 < KIN; k0 += 64) {
#pragma unroll
        for (int l = 0; l < 4; l++) {
            int idx = tid + l * 256;
            int r = idx >> 3, q = idx & 7;
            uint4 v = *(const uint4*)(g_x16 + (size_t)(n0 + r) * KIN + k0 + q * 8);
            *(uint4*)(xs + r * XP + q * 8) = v;
        }
#pragma unroll
        for (int l = 0; l < 2; l++) {
            int idx = tid + l * 256;
            int r = idx >> 3, q = idx & 7;
            uint4 v = *(const uint4*)(g_W16 + ((size_t)h * KIN + k0 + r) * DOUT + q * 8);
            *(uint4*)(ws + r * WP + q * 8) = v;
        }
        __syncthreads();

        const int rsel = lane & 15, csel = (lane >> 4) << 3;
#pragma unroll
        for (int kk = 0; kk < 64; kk += 16) {
            unsigned a0[4], a1f[4], b0[4], b1[4];
            LDSM_X4 (a0,  Xb + ((mblk      + rsel) * XP + kk + csel) * 2);
            LDSM_X4 (a1f, Xb + ((mblk + 16 + rsel) * XP + kk + csel) * 2);
            LDSM_X4T(b0,  Wb + ((kk + rsel) * WP + nblk      + csel) * 2);
            LDSM_X4T(b1,  Wb + ((kk + rsel) * WP + nblk + 16 + csel) * 2);
            MMA16816(acc[0][0], a0,  b0 + 0);
            MMA16816(acc[0][1], a0,  b0 + 2);
            MMA16816(acc[0][2], a0,  b1 + 0);
            MMA16816(acc[0][3], a0,  b1 + 2);
            MMA16816(acc[1][0], a1f, b0 + 0);
            MMA16816(acc[1][1], a1f, b0 + 2);
            MMA16816(acc[1][2], a1f, b1 + 0);
            MMA16816(acc[1][3], a1f, b1 + 2);
        }
        __syncthreads();
    }

    const int g = lane >> 2, t2 = (lane & 3) * 2;
    float*  of  = g_Wh   + ((size_t)h * NV + n0) * DOUT;
    __half* o16 = g_Wh16 + ((size_t)h * NV + n0) * DOUT;

    float s1A[2] = {0.f, 0.f}, s1B[2] = {0.f, 0.f};
    float s2A[2] = {0.f, 0.f}, s2B[2] = {0.f, 0.f};
    const float* a1g = a1 + h * DOUT;
    const float* a2g = a2 + h * DOUT;

#pragma unroll
    for (int mi = 0; mi < 2; mi++)
#pragma unroll
        for (int nj = 0; nj < 4; nj++) {
            int rA = mblk + mi * 16 + g, rB = rA + 8;
            int col = nblk + nj * 8 + t2;
            *(float2*)(of + (size_t)rA * DOUT + col) =
                make_float2(acc[mi][nj][0], acc[mi][nj][1]);
            *(float2*)(of + (size_t)rB * DOUT + col) =
                make_float2(acc[mi][nj][2], acc[mi][nj][3]);
            *(__half2*)(o16 + (size_t)rA * DOUT + col) =
                __floats2half2_rn(acc[mi][nj][0], acc[mi][nj][1]);
            *(__half2*)(o16 + (size_t)rB * DOUT + col) =
                __floats2half2_rn(acc[mi][nj][2], acc[mi][nj][3]);

            float a1c0 = a1g[col], a1c1 = a1g[col + 1];
            float a2c0 = a2g[col], a2c1 = a2g[col + 1];
            s1A[mi] += acc[mi][nj][0] * a1c0 + acc[mi][nj][1] * a1c1;
            s2A[mi] += acc[mi][nj][0] * a2c0 + acc[mi][nj][1] * a2c1;
            s1B[mi] += acc[mi][nj][2] * a1c0 + acc[mi][nj][3] * a1c1;
            s2B[mi] += acc[mi][nj][2] * a2c0 + acc[mi][nj][3] * a2c1;
        }

    // quad-reduce (lanes differing in lane&3 hold different col groups)
#pragma unroll
    for (int off = 1; off <= 2; off <<= 1) {
#pragma unroll
        for (int mi = 0; mi < 2; mi++) {
            s1A[mi] += __shfl_xor_sync(0xffffffffu, s1A[mi], off);
            s1B[mi] += __shfl_xor_sync(0xffffffffu, s1B[mi], off);
            s2A[mi] += __shfl_xor_sync(0xffffffffu, s2A[mi], off);
            s2B[mi] += __shfl_xor_sync(0xffffffffu, s2B[mi], off);
        }
    }

    // cross-warp (nblk 0/1) combine via reused smem
    float* part1 = (float*)xs;          // [2][128]
    float* part2 = part1 + 256;         // [2][128]
    float* red   = part2 + 256;         // [128]
    if ((lane & 3) == 0) {
        int nb = wid >> 2;
#pragma unroll
        for (int mi = 0; mi < 2; mi++) {
            int rA = mblk + mi * 16 + g;
            part1[nb * 128 + rA]     = s1A[mi];
            part1[nb * 128 + rA + 8] = s1B[mi];
            part2[nb * 128 + rA]     = s2A[mi];
            part2[nb * 128 + rA + 8] = s2B[mi];
        }
    }
    __syncthreads();
    if (tid < 128) {
        float s1 = part1[tid] + part1[128 + tid];
        float s2 = part2[tid] + part2[128 + tid];
        g_f1[(size_t)h * NV + n0 + tid] = s1;
        g_f2[(size_t)h * NV + n0 + tid] = s2;
        red[tid] = s2;
    }
    __syncthreads();
    if (tid < 32) {
        float m = fmaxf(red[tid], red[tid + 32]);
        m = fmaxf(m, fmaxf(red[tid + 64], red[tid + 96]));
#pragma unroll
        for (int off = 16; off; off >>= 1)
            m = fmaxf(m, __shfl_xor_sync(0xffffffffu, m, off));
        if (tid == 0) atomicMax(&g_F2maxU[h], fkey(m));
    }
}

// ---------------------------------------------------------------------------
// E1/E05 precompute (after wh16's fused fvec)
// ---------------------------------------------------------------------------
__global__ __launch_bounds__(256) void e_kernel() {
    int i = blockIdx.x * 256 + threadIdx.x;                  // 0..32767
    int h = i >> 12;
    float d = g_f2[i] - funkey(g_F2maxU[h]);
    g_E1[i]  = __expf(d);
    g_E05[i] = __expf(LALPHA * d);
}

// ---------------------------------------------------------------------------
// Kernel 3: fused softmax + aggregation via mma.sync.
//   p = exp(lrelu(f1+f2) - Mr) = max(c1*E1[m], c2*E05[m])  (exact, all <= 1)
// Mask: transposed gmem layout, 1 coalesced LDG/warp/chunk + shfl in k-loop.
// Double-buffered P/W tiles, ONE barrier per chunk. Denominator via ones-MMA.
// smem 56.3KB -> 2 CTAs/SM.
// ---------------------------------------------------------------------------
#define PP 72

#define SM_P    0         /* 2 x 18432 */
#define SM_W    36864     /* 2 x 9216  */
#define SM_C1   55296     /* 128 f */
#define SM_C2   55808     /* 128 f */
#define SMEM_ATT 56320

__global__ __launch_bounds__(256, 2) void attn_mma(float* __restrict__ out) {
    extern __shared__ unsigned char sm[];
    float* c1s = (float*)(sm + SM_C1);
    float* c2s = (float*)(sm + SM_C2);

    const int h = blockIdx.x, n0 = blockIdx.y * 128;
    const int tid = threadIdx.x, wid = tid >> 5, lane = tid & 31;

    const uint32_t Pb = smem_u32(sm + SM_P);
    const uint32_t Wb = smem_u32(sm + SM_W);

    if (tid < 128) {
        float t = g_f1[(size_t)h * NV + n0 + tid] + funkey(g_F2maxU[h]);
        float Mr = fmaxf(t, LALPHA * t);
        c1s[tid] = __expf(t - Mr);
        c2s[tid] = __expf(LALPHA * t - Mr);
    }
    __syncthreads();

    const int mblk = (wid & 3) * 32, nblk = (wid >> 2) * 32;
    float acc[2][4][4];
#pragma unroll
    for (int i = 0; i < 2; i++)
#pragma unroll
        for (int j = 0; j < 4; j++)
#pragma unroll
            for (int q = 0; q < 4; q++) acc[i][j][q] = 0.f;
    float denacc[2][4] = {{0.f, 0.f, 0.f, 0.f}, {0.f, 0.f, 0.f, 0.f}};
    const unsigned onesb[2] = {0x3C003C00u, 0x3C003C00u};

    const __half* WhH = g_Wh16 + (size_t)h * NV * DOUT;
    const float*  E1g = g_E1  + (size_t)h * NV;
    const float*  E5g = g_E05 + (size_t)h * NV;

    for (int c = 0; c < 64; c++) {
        const int buf = c & 1;

        // Wh chunk rows into registers first (MLP)
        uint4 bv[2];
#pragma unroll
        for (int l = 0; l < 2; l++) {
            int idx = tid + l * 256;
            int m = idx >> 3, q = idx & 7;
            bv[l] = *(const uint4*)(WhH + (size_t)(c * 64 + m) * DOUT + q * 8);
        }

        // mask: one coalesced word per lane per chunk (transposed layout)
        unsigned mw = g_mask[(size_t)(2 * c + (lane & 1)) * NV +
                             n0 + wid * 16 + (lane >> 1)];

        // P tile: warp wid -> rows wid*16..+15; lane -> m-pair (2*lane, 2*lane+1)
        float2 e1p = *(const float2*)(E1g + c * 64 + 2 * lane);
        float2 e5p = *(const float2*)(E5g + c * 64 + 2 * lane);
#pragma unroll
        for (int k = 0; k < 16; k++) {
            int r = wid * 16 + k;
            unsigned w = __shfl_sync(0xffffffffu, mw, 2 * k + (lane >> 4));
            float C1 = c1s[r], C2 = c2s[r];
            float p0 = fmaxf(C1 * e1p.x, C2 * e5p.x);
            float p1 = fmaxf(C1 * e1p.y, C2 * e5p.y);
            p0 = ((w >> ((2 * lane) & 31)) & 1u) ? p0 : 0.f;
            p1 = ((w >> ((2 * lane + 1) & 31)) & 1u) ? p1 : 0.f;
            *(__half2*)(sm + SM_P + buf * 18432 + (r * PP + 2 * lane) * 2) =
                __floats2half2_rn(p0, p1);
        }

        // Wh tile store
#pragma unroll
        for (int l = 0; l < 2; l++) {
            int idx = tid + l * 256;
            int m = idx >> 3, q = idx & 7;
            *(uint4*)(sm + SM_W + buf * 9216 + (m * PP + q * 8) * 2) = bv[l];
        }
        __syncthreads();   // buf[c] tiles ready; buf[(c+1)&1] free (see analysis)

        // HMMA: M=128 N=64 K=64 (+ ones-column MMAs for denominator)
        const uint32_t Pbb = Pb + buf * 18432;
        const uint32_t Wbb = Wb + buf * 9216;
        const int rsel = lane & 15, csel = (lane >> 4) << 3;
#pragma unroll
        for (int k0 = 0; k0 < 64; k0 += 16) {
            unsigned a0[4], a1f[4], b0[4], b1[4];
            LDSM_X4 (a0,  Pbb + ((mblk      + rsel) * PP + k0 + csel) * 2);
            LDSM_X4 (a1f, Pbb + ((mblk + 16 + rsel) * PP + k0 + csel) * 2);
            LDSM_X4T(b0,  Wbb + ((k0 + rsel) * PP + nblk      + csel) * 2);
            LDSM_X4T(b1,  Wbb + ((k0 + rsel) * PP + nblk + 16 + csel) * 2);
            MMA16816(acc[0][0], a0,  b0 + 0);
            MMA16816(acc[0][1], a0,  b0 + 2);
            MMA16816(acc[0][2], a0,  b1 + 0);
            MMA16816(acc[0][3], a0,  b1 + 2);
            MMA16816(acc[1][0], a1f, b0 + 0);
            MMA16816(acc[1][1], a1f, b0 + 2);
            MMA16816(acc[1][2], a1f, b1 + 0);
            MMA16816(acc[1][3], a1f, b1 + 2);
            MMA16816(denacc[0], a0,  onesb);
            MMA16816(denacc[1], a1f, onesb);
        }
    }

    // epilogue: den comes straight from the ones-MMA fragments (same rows)
    const int g = lane >> 2, t2 = (lane & 3) * 2;
#pragma unroll
    for (int mi = 0; mi < 2; mi++) {
        float ia = denacc[mi][0] > 0.f ? 1.f / denacc[mi][0] : 0.f;
        float ib = denacc[mi][2] > 0.f ? 1.f / denacc[mi][2] : 0.f;
#pragma unroll
        for (int nj = 0; nj < 4; nj++) {
            int rA = mblk + mi * 16 + g;
            int rB = rA + 8;
            int col = nblk + nj * 8 + t2;
            *(float2*)(out + (size_t)(n0 + rA) * (NHEAD * DOUT) + h * DOUT + col) =
                make_float2(acc[mi][nj][0] * ia, acc[mi][nj][1] * ia);
            *(float2*)(out + (size_t)(n0 + rB) * (NHEAD * DOUT) + h * DOUT + col) =
                make_float2(acc[mi][nj][2] * ib, acc[mi][nj][3] * ib);
        }
    }
}

// ---------------------------------------------------------------------------
extern "C" void kernel_launch(void* const* d_in, const int* in_sizes, int n_in,
                              void* d_out, int out_size) {
    (void)in_sizes; (void)n_in; (void)out_size;
    const float* x   = (const float*)d_in[0];
    const int*   adj = (const int*)d_in[1];
    const float* W   = (const float*)d_in[2];
    const float* a1  = (const float*)d_in[3];
    const float* a2  = (const float*)d_in[4];
    float* out = (float*)d_out;

    cudaFuncSetAttribute(attn_mma, cudaFuncAttributeMaxDynamicSharedMemorySize,
                         SMEM_ATT);

    prep_kernel<<<256, 256>>>(x, W);
    mask_kernel<<<512, 256>>>(adj);
    wh16_kernel<<<dim3(32, 8), 256>>>(a1, a2);
    e_kernel<<<128, 256>>>();
    attn_mma<<<dim3(8, 32), 256, SMEM_ATT>>>(out);
}